// round 1
// baseline (speedup 1.0000x reference)
#include <cuda_runtime.h>
#include <cstdint>

// PeakAligner constants (from reference):
//   FACTOR=3, IPS=64, BP=5, CENTER=72, LO=57, HI=87, NEW_CENTER=57, ALIGNED_LEN=192
//   L=220 (fixed by problem), window = [57,87) -> 30 elements
//   start = index_max - 57 in [0,29]; in_bounds <=> start <= 28; safe_start = min(start,28)
//   valid  <=> (argmax of 192-window == 57) && in_bounds
//   downsample indices: safe_start + 3*i, i=0..63

#define L_DIM 220
#define WIN_LO 57
#define WIN_LEN 30
#define ALIGNED_LEN 192
#define NEW_CENTER 57
#define MAX_START 28
#define ROWS_PER_BLOCK 8
#define THREADS 256

// Map float to monotone-orderable unsigned (handles negatives; data has no NaN)
__device__ __forceinline__ unsigned ford(float f) {
    unsigned u = __float_as_uint(f);
    return (u & 0x80000000u) ? ~u : (u | 0x80000000u);
}

__global__ __launch_bounds__(THREADS)
void peak_aligner_kernel(const float* __restrict__ in,
                         float* __restrict__ out,
                         float* __restrict__ mask_out,
                         int K) {
    __shared__ float s[ROWS_PER_BLOCK][L_DIM];   // 7040 B, no padding needed

    const int row0 = blockIdx.x * ROWS_PER_BLOCK;
    const int rows_here = min(ROWS_PER_BLOCK, K - row0);

    // ---- Phase A: coalesced float4 load of full rows into shared ----
    // Each row is 880 bytes (16B aligned), 55 float4 per row.
    {
        const float4* gin = reinterpret_cast<const float4*>(in + (size_t)row0 * L_DIM);
        float4* s4 = reinterpret_cast<float4*>(&s[0][0]);
        const int total4 = rows_here * (L_DIM / 4);          // up to 440
        for (int i = threadIdx.x; i < total4; i += THREADS)
            s4[i] = gin[i];
    }
    __syncthreads();

    const int w    = threadIdx.x >> 5;
    const int lane = threadIdx.x & 31;
    const int row  = row0 + w;
    if (w >= rows_here) return;

    const float* r = s[w];

    // ---- Step 1: argmax over window [57, 87)  (first occurrence) ----
    float wv = (lane < WIN_LEN) ? r[WIN_LO + lane] : -__int_as_float(0x7f800000); // -inf
    // key: high 32 = orderable value, low bits = (255 - lane) so ties pick min lane
    unsigned long long key = ((unsigned long long)ford(wv) << 32) | (unsigned)(255 - lane);
    #pragma unroll
    for (int o = 16; o; o >>= 1) {
        unsigned long long other = __shfl_xor_sync(0xFFFFFFFFu, key, o);
        if (other > key) key = other;
    }
    const int start = 255 - (int)(key & 0xFFu);   // local_peak == start (index_max - 57)
    const bool in_bounds = (start <= MAX_START);
    const int ss = min(start, MAX_START);         // safe_start

    // ---- Step 2: argmax (first occurrence) over r[ss .. ss+191] ----
    float m = -__int_as_float(0x7f800000);
    int   mi = 0x7FFF;
    #pragma unroll
    for (int j = 0; j < 6; j++) {
        const int i = lane + 32 * j;
        const float x = r[ss + i];
        if (x > m) { m = x; mi = i; }             // strict > keeps first occurrence in-lane
    }
    unsigned long long key2 = ((unsigned long long)ford(m) << 32) | (unsigned)(0xFFFF - mi);
    #pragma unroll
    for (int o = 16; o; o >>= 1) {
        unsigned long long other = __shfl_xor_sync(0xFFFFFFFFu, key2, o);
        if (other > key2) key2 = other;
    }
    const int arg = 0xFFFF - (int)(key2 & 0xFFFFu);
    const bool valid = (arg == NEW_CENTER) && in_bounds;

    // ---- Step 3: downsampled output (stride-3 gather from shared) + mask ----
    const float o0 = valid ? r[ss + 3 * lane]        : 0.0f;
    const float o1 = valid ? r[ss + 3 * (lane + 32)] : 0.0f;
    float* orow = out + (size_t)row * 64;
    orow[lane]      = o0;
    orow[lane + 32] = o1;
    if (lane == 0)
        mask_out[row] = valid ? 0.0f : 1.0f;      // removed_mask = !valid
}

extern "C" void kernel_launch(void* const* d_in, const int* in_sizes, int n_in,
                              void* d_out, int out_size) {
    const float* in = (const float*)d_in[0];
    const int K = in_sizes[0] / L_DIM;
    float* out  = (float*)d_out;
    float* mask = out + (size_t)K * 64;           // concatenated second output
    const int blocks = (K + ROWS_PER_BLOCK - 1) / ROWS_PER_BLOCK;
    peak_aligner_kernel<<<blocks, THREADS>>>(in, out, mask, K);
}

// round 2
// speedup vs baseline: 1.5960x; 1.5960x over previous
#include <cuda_runtime.h>
#include <cstdint>

// PeakAligner constants (from reference):
//   FACTOR=3, IPS=64, BP=5, CENTER=72, LO=57, HI=87, NEW_CENTER=57, ALIGNED_LEN=192
//   L=220, window=[57,87) -> 30 elems
//   start = index_max-57 in [0,29]; in_bounds <=> start<=28; ss = min(start,28)
//   valid <=> (first-argmax of r[ss..ss+191] == 57) && in_bounds
//   downsample: r[ss + 3*i], i=0..63

#define L_DIM 220
#define WIN_LO 57
#define WIN_LEN 30
#define NEW_CENTER 57
#define MAX_START 28
#define ROWS_PER_BLOCK 8
#define THREADS 256

__device__ __forceinline__ unsigned ford(float f) {
    unsigned u = __float_as_uint(f);
    return u ^ (unsigned)(((int)u >> 31) | 0x80000000);
}

__global__ __launch_bounds__(THREADS)
void peak_aligner_kernel(const float* __restrict__ in,
                         float* __restrict__ out,
                         float* __restrict__ mask_out,
                         int K) {
    // 8 rows * 220 floats, +4 floats slack: step-2 vector loads may touch up to
    // element 223 of the last row; those values are always range-masked out.
    __shared__ float s[ROWS_PER_BLOCK * L_DIM + 4];

    const int row0 = blockIdx.x * ROWS_PER_BLOCK;
    const int rows_here = min(ROWS_PER_BLOCK, K - row0);

    // ---- Phase A: cp.async 16B copies, fully coalesced (55 float4 per row) ----
    {
        const float4* gin = reinterpret_cast<const float4*>(in + (size_t)row0 * L_DIM);
        const int total4 = rows_here * (L_DIM / 4);          // up to 440
        for (int i = threadIdx.x; i < total4; i += THREADS) {
            uint32_t saddr = (uint32_t)__cvta_generic_to_shared(
                reinterpret_cast<float4*>(s) + i);
            asm volatile("cp.async.cg.shared.global [%0], [%1], 16;\n"
                         :: "r"(saddr), "l"(gin + i));
        }
        asm volatile("cp.async.commit_group;\n");
        asm volatile("cp.async.wait_group 0;\n" ::: "memory");
    }
    __syncthreads();

    const int w    = threadIdx.x >> 5;
    const int lane = threadIdx.x & 31;
    const int row  = row0 + w;
    if (w >= rows_here) return;

    const float* r = s + w * L_DIM;
    const float NEG_INF = __uint_as_float(0xff800000u);

    // ---- Step 1: first-argmax over window [57,87) via redux + ballot ----
    {
        // computed below into 'start'
    }
    float wv = (lane < WIN_LEN) ? r[WIN_LO + lane] : NEG_INF;
    unsigned wu = (lane < WIN_LEN) ? ford(wv) : 0u;
    unsigned wmax = __reduce_max_sync(0xffffffffu, wu);
    unsigned wb = __ballot_sync(0xffffffffu, wu == wmax);
    const int start = __ffs(wb) - 1;                // min lane attaining max
    const bool in_bounds = (start <= MAX_START);
    const int ss = min(start, MAX_START);
    const int a  = ss & ~3;                          // 16B-aligned base, a in {0,4,...,28}

    // ---- Step 2: first-argmax over r[ss..ss+191] using aligned LDS.128 ----
    float m = NEG_INF;
    int   rel_best = 1023;
    {
        const float4 v0 = *reinterpret_cast<const float4*>(r + a + 4 * lane);
        const int rel0 = a + 4 * lane - ss;          // in [-3, 124]
        const float e0[4] = {v0.x, v0.y, v0.z, v0.w};
        #pragma unroll
        for (int k = 0; k < 4; k++) {
            const int rel = rel0 + k;
            if ((unsigned)rel < 192u && e0[k] > m) { m = e0[k]; rel_best = rel; }
        }
        if (lane < 17) {                             // lanes >=17: rel >= 192 always
            const float4 v1 = *reinterpret_cast<const float4*>(r + a + 128 + 4 * lane);
            const float e1[4] = {v1.x, v1.y, v1.z, v1.w};
            #pragma unroll
            for (int k = 0; k < 4; k++) {
                const int rel = rel0 + 128 + k;
                if ((unsigned)rel < 192u && e1[k] > m) { m = e1[k]; rel_best = rel; }
            }
        }
    }
    const unsigned um   = ford(m);
    const unsigned gmax = __reduce_max_sync(0xffffffffu, um);
    const unsigned cand = (um == gmax) ? (unsigned)rel_best : 1023u;
    const unsigned arg  = __reduce_min_sync(0xffffffffu, cand);
    const bool valid = (arg == NEW_CENTER) && in_bounds;

    // ---- Step 3: downsampled output (stride-3, conflict-free) + mask ----
    const float o0 = valid ? r[ss + 3 * lane]      : 0.0f;
    const float o1 = valid ? r[ss + 3 * lane + 96] : 0.0f;
    float* orow = out + (size_t)row * 64;
    orow[lane]      = o0;
    orow[lane + 32] = o1;
    if (lane == 0)
        mask_out[row] = valid ? 0.0f : 1.0f;         // removed_mask = !valid
}

extern "C" void kernel_launch(void* const* d_in, const int* in_sizes, int n_in,
                              void* d_out, int out_size) {
    const float* in = (const float*)d_in[0];
    const int K = in_sizes[0] / L_DIM;
    float* out  = (float*)d_out;
    float* mask = out + (size_t)K * 64;
    const int blocks = (K + ROWS_PER_BLOCK - 1) / ROWS_PER_BLOCK;
    peak_aligner_kernel<<<blocks, THREADS>>>(in, out, mask, K);
}

// round 3
// speedup vs baseline: 1.8270x; 1.1447x over previous
#include <cuda_runtime.h>
#include <cstdint>

// PeakAligner constants:
//   L=220, window=[57,87) -> 30 elems; start=index_max-57 in [0,29]
//   in_bounds <=> start<=28; ss=min(start,28)
//   valid <=> first-argmax of r[ss..ss+191] == 57 && in_bounds
//         <=> r[ss+57]==max(192) && max(first 57) < max(192) && in_bounds
//   downsample: r[ss+3*i], i=0..63

#define L_DIM 220
#define WIN_LO 57
#define WIN_LEN 30
#define MAX_START 28
#define ROWS_PER_BLOCK 8
#define THREADS 256

__device__ __forceinline__ unsigned ford(float f) {
    unsigned u = __float_as_uint(f);
    return u ^ (unsigned)(((int)u >> 31) | 0x80000000);
}
__device__ __forceinline__ float unford(unsigned t) {
    unsigned u = (t & 0x80000000u) ? (t ^ 0x80000000u) : ~t;
    return __uint_as_float(u);
}

__global__ __launch_bounds__(THREADS)
void peak_aligner_kernel(const float* __restrict__ in,
                         float* __restrict__ out,
                         float* __restrict__ mask_out,
                         int K) {
    __shared__ float s[ROWS_PER_BLOCK * L_DIM];

    const int row0 = blockIdx.x * ROWS_PER_BLOCK;
    const int rows_here = min(ROWS_PER_BLOCK, K - row0);
    const int total4 = rows_here * (L_DIM / 4);              // 440 when full

    // ---- Phase A: cp.async 16B, fully coalesced; exactly 2 issues/thread ----
    {
        const float4* gin = reinterpret_cast<const float4*>(in + (size_t)row0 * L_DIM);
        int i = threadIdx.x;
        if (i < total4) {
            uint32_t sa = (uint32_t)__cvta_generic_to_shared(
                reinterpret_cast<float4*>(s) + i);
            asm volatile("cp.async.cg.shared.global [%0], [%1], 16;\n"
                         :: "r"(sa), "l"(gin + i));
        }
        i += THREADS;
        if (i < total4) {
            uint32_t sa = (uint32_t)__cvta_generic_to_shared(
                reinterpret_cast<float4*>(s) + i);
            asm volatile("cp.async.cg.shared.global [%0], [%1], 16;\n"
                         :: "r"(sa), "l"(gin + i));
        }
        asm volatile("cp.async.commit_group;\n");
        asm volatile("cp.async.wait_group 0;\n" ::: "memory");
    }
    __syncthreads();

    const int w    = threadIdx.x >> 5;
    const int lane = threadIdx.x & 31;
    const int row  = row0 + w;
    if (w >= rows_here) return;

    const float* r = s + w * L_DIM;
    const float NEG_INF = __uint_as_float(0xff800000u);

    // ---- Step 1: argmax index over window [57,87) (first occurrence) ----
    const float wv = (lane < WIN_LEN) ? r[WIN_LO + lane] : NEG_INF;
    const unsigned wu = (lane < WIN_LEN) ? ford(wv) : 0u;
    const unsigned wmax = __reduce_max_sync(0xffffffffu, wu);
    const unsigned wb = __ballot_sync(0xffffffffu, wu == wmax);
    const int start = __ffs(wb) - 1;
    const bool in_bounds = (start <= MAX_START);
    const int ss = min(start, MAX_START);

    // ---- Step 2: valid <=> v57==M(0..191) && P(0..56)<M ----
    const float* p = r + ss;
    const float x0 = p[lane];
    const float x1 = p[lane + 32];
    const float x2 = p[lane + 64];
    const float x3 = p[lane + 96];
    const float x4 = p[lane + 128];
    const float x5 = p[lane + 160];
    const float Ml = fmaxf(fmaxf(fmaxf(x0, x1), fmaxf(x2, x3)), fmaxf(x4, x5));
    const float Pl = (lane < 25) ? fmaxf(x0, x1) : x0;   // rel<57: j=0 all, j=1 lane<25
    const float M = unford(__reduce_max_sync(0xffffffffu, ford(Ml)));
    const float P = unford(__reduce_max_sync(0xffffffffu, ford(Pl)));
    const float v57 = p[57];                              // broadcast LDS
    const bool valid = (v57 == M) && (P < M) && in_bounds;

    // ---- Step 3: downsample (stride-3, conflict-free) + mask, streamed ----
    const float o0 = valid ? p[3 * lane]      : 0.0f;
    const float o1 = valid ? p[3 * lane + 96] : 0.0f;
    float* orow = out + (size_t)row * 64;
    __stcs(orow + lane,      o0);
    __stcs(orow + lane + 32, o1);
    if (lane == 0)
        __stcs(mask_out + row, valid ? 0.0f : 1.0f);      // removed_mask = !valid
}

extern "C" void kernel_launch(void* const* d_in, const int* in_sizes, int n_in,
                              void* d_out, int out_size) {
    const float* in = (const float*)d_in[0];
    const int K = in_sizes[0] / L_DIM;
    float* out  = (float*)d_out;
    float* mask = out + (size_t)K * 64;
    const int blocks = (K + ROWS_PER_BLOCK - 1) / ROWS_PER_BLOCK;
    peak_aligner_kernel<<<blocks, THREADS>>>(in, out, mask, K);
}

// round 4
// speedup vs baseline: 1.9654x; 1.0758x over previous
#include <cuda_runtime.h>
#include <cstdint>

// PeakAligner: L=220, window=[57,87); start=index_max-57 in [0,29]
//   in_bounds <=> start<=28; ss=min(start,28)
//   valid <=> r[ss+57]==max(r[ss..ss+191]) && max(r[ss..ss+56]) < that max && in_bounds
//   downsample: r[ss+3*i], i=0..63

#define L_DIM 220
#define WIN_LO 57
#define WIN_LEN 30
#define MAX_START 28
#define ROWS_PER_TILE 8
#define TILES_PER_BLOCK 4
#define THREADS 256
#define FLOATS_PER_TILE (ROWS_PER_TILE * L_DIM)   // 1760
#define VEC4_PER_TILE (FLOATS_PER_TILE / 4)       // 440

__device__ __forceinline__ unsigned ford(float f) {
    unsigned u = __float_as_uint(f);
    return u ^ (unsigned)(((int)u >> 31) | 0x80000000);
}
__device__ __forceinline__ float unford(unsigned t) {
    unsigned u = (t & 0x80000000u) ? (t ^ 0x80000000u) : ~t;
    return __uint_as_float(u);
}

__device__ __forceinline__ void prefetch_tile(float* sbuf, const float* __restrict__ in,
                                              long long row0, int rows_here) {
    const float4* gin = reinterpret_cast<const float4*>(in + row0 * L_DIM);
    const int total4 = rows_here * (L_DIM / 4);
    int i = threadIdx.x;
    if (i < total4) {
        uint32_t sa = (uint32_t)__cvta_generic_to_shared(reinterpret_cast<float4*>(sbuf) + i);
        asm volatile("cp.async.cg.shared.global [%0], [%1], 16;\n" :: "r"(sa), "l"(gin + i));
    }
    i += THREADS;
    if (i < total4) {
        uint32_t sa = (uint32_t)__cvta_generic_to_shared(reinterpret_cast<float4*>(sbuf) + i);
        asm volatile("cp.async.cg.shared.global [%0], [%1], 16;\n" :: "r"(sa), "l"(gin + i));
    }
    asm volatile("cp.async.commit_group;\n");
}

__global__ __launch_bounds__(THREADS)
void peak_aligner_kernel(const float* __restrict__ in,
                         float* __restrict__ out,
                         float* __restrict__ mask_out,
                         int K, int total_tiles) {
    __shared__ float s[2][FLOATS_PER_TILE];

    const int w    = threadIdx.x >> 5;
    const int lane = threadIdx.x & 31;
    const float NEG_INF = __uint_as_float(0xff800000u);

    int tile = blockIdx.x * TILES_PER_BLOCK;
    if (tile >= total_tiles) return;

    // prime the pipeline
    {
        const long long r0 = (long long)tile * ROWS_PER_TILE;
        prefetch_tile(s[0], in, r0, min(ROWS_PER_TILE, K - (int)r0));
    }

    #pragma unroll 1
    for (int t = 0; t < TILES_PER_BLOCK; t++, tile++) {
        const bool have_next = (t + 1 < TILES_PER_BLOCK) && (tile + 1 < total_tiles);
        if (have_next) {
            const long long r0n = (long long)(tile + 1) * ROWS_PER_TILE;
            prefetch_tile(s[(t + 1) & 1], in, r0n, min(ROWS_PER_TILE, K - (int)r0n));
            asm volatile("cp.async.wait_group 1;\n" ::: "memory");
        } else {
            asm volatile("cp.async.wait_group 0;\n" ::: "memory");
        }
        __syncthreads();

        const int row0 = tile * ROWS_PER_TILE;
        const int rows_here = min(ROWS_PER_TILE, K - row0);
        if (w < rows_here) {
            const float* r = s[t & 1] + w * L_DIM;
            const int row = row0 + w;

            // Step 1: first-argmax over window [57,87)
            const unsigned wu = (lane < WIN_LEN) ? ford(r[WIN_LO + lane]) : 0u;
            const unsigned wmax = __reduce_max_sync(0xffffffffu, wu);
            const unsigned wb = __ballot_sync(0xffffffffu, wu == wmax);
            const int start = __ffs(wb) - 1;
            const bool in_bounds = (start <= MAX_START);
            const int ss = min(start, MAX_START);

            // Step 2: valid <=> v57==M(0..191) && P(0..56)<M
            const float* p = r + ss;
            const float x0 = p[lane];
            const float x1 = p[lane + 32];
            const float x2 = p[lane + 64];
            const float x3 = p[lane + 96];
            const float x4 = p[lane + 128];
            const float x5 = p[lane + 160];
            const float Ml = fmaxf(fmaxf(fmaxf(x0, x1), fmaxf(x2, x3)), fmaxf(x4, x5));
            const float Pl = (lane < 25) ? fmaxf(x0, x1) : x0;
            const float M = unford(__reduce_max_sync(0xffffffffu, ford(Ml)));
            const float P = unford(__reduce_max_sync(0xffffffffu, ford(Pl)));
            const float v57 = p[57];
            const bool valid = (v57 == M) && (P < M) && in_bounds;

            // Step 3: downsample + mask (streaming stores)
            const float o0 = valid ? p[3 * lane]      : 0.0f;
            const float o1 = valid ? p[3 * lane + 96] : 0.0f;
            float* orow = out + (size_t)row * 64;
            __stcs(orow + lane,      o0);
            __stcs(orow + lane + 32, o1);
            if (lane == 0)
                __stcs(mask_out + row, valid ? 0.0f : 1.0f);
        }
        __syncthreads();   // all warps done with s[t&1] before it is refilled
    }
}

extern "C" void kernel_launch(void* const* d_in, const int* in_sizes, int n_in,
                              void* d_out, int out_size) {
    const float* in = (const float*)d_in[0];
    const int K = in_sizes[0] / L_DIM;
    float* out  = (float*)d_out;
    float* mask = out + (size_t)K * 64;
    const int total_tiles = (K + ROWS_PER_TILE - 1) / ROWS_PER_TILE;
    const int blocks = (total_tiles + TILES_PER_BLOCK - 1) / TILES_PER_BLOCK;
    peak_aligner_kernel<<<blocks, THREADS>>>(in, out, mask, K, total_tiles);
}